// round 6
// baseline (speedup 1.0000x reference)
#include <cuda_runtime.h>
#include <cuda_fp16.h>
#include <cstdint>
#include <math.h>

#define BATCH   65536
#define NUMC    512
#define DIM     256
#define BM      128
#define BN      128
#define NT      (NUMC/BN)      // 4
#define THREADS 256
#define NBLOCKS (BATCH/BM)     // 512
#define ALPHA   0.05f
#define FINF    3.402823466e38f

// smem byte offsets
#define SAS     0              // A tile fp16 128x256 swizzled       (65536)
#define SB0     65536          // B buf 0                            (65536)
#define SB1     131072         // B buf 1                            (65536)
#define SCSQ    196608         // 512 f                              (2048)
#define SMV     198656         // 128x2 f                            (1024)
#define SMI     199680         // 128x2 i                            (1024)
#define SIDX    200704         // 128 i                              (512)
#define SDST    201216         // 128 f                              (512)
#define SMEM_TOTAL 201728

__device__ float g_csq[NUMC];
__device__ __align__(16) uint32_t g_cenH[NUMC * DIM / 2];  // f16x2, [n][k]
__device__ float g_partials[NBLOCKS];

// ---------------- helpers ----------------
__device__ __forceinline__ uint32_t smem_u32(const void* p) {
    uint32_t a;
    asm("{ .reg .u64 t; cvta.to.shared.u64 t, %1; cvt.u32.u64 %0, t; }"
        : "=r"(a) : "l"(p));
    return a;
}
__device__ __forceinline__ uint32_t f16pair(float lo, float hi) {
    uint32_t r;
    asm("cvt.rn.f16x2.f32 %0, %1, %2;" : "=r"(r) : "f"(hi), "f"(lo));
    return r;
}
// m16n8k16 f16 inputs, f16 accumulators (2 C regs)
__device__ __forceinline__ void mma_h(uint32_t c[2], const uint32_t a[4],
                                      uint32_t b0, uint32_t b1) {
    asm volatile(
        "mma.sync.aligned.m16n8k16.row.col.f16.f16.f16.f16 "
        "{%0,%1}, {%2,%3,%4,%5}, {%6,%7}, {%0,%1};"
        : "+r"(c[0]), "+r"(c[1])
        : "r"(a[0]), "r"(a[1]), "r"(a[2]), "r"(a[3]), "r"(b0), "r"(b1));
}
#define CP_ASYNC16(dst, src) \
    asm volatile("cp.async.cg.shared.global [%0], [%1], 16;" :: "r"(dst), "l"(src))
#define CP_COMMIT()  asm volatile("cp.async.commit_group;" ::: "memory")
#define CP_WAIT0()   asm volatile("cp.async.wait_group 0;" ::: "memory")

// ---------------------------------------------------------------------------
// Kernel 0: center norms (exact fp32) + fp16 copy of centers, [n][k] layout.
// ---------------------------------------------------------------------------
__global__ void prep_kernel(const float* __restrict__ cen) {
    int w    = blockIdx.x * 8 + (threadIdx.x >> 5);
    int lane = threadIdx.x & 31;
    const float2* row = (const float2*)(cen + (size_t)w * DIM);
    float s = 0.f;
    #pragma unroll
    for (int i = 0; i < 4; i++) {
        float2 v = row[lane + 32 * i];
        s += v.x * v.x + v.y * v.y;
        g_cenH[w * (DIM / 2) + lane + 32 * i] = f16pair(v.x, v.y);
    }
    #pragma unroll
    for (int off = 16; off; off >>= 1)
        s += __shfl_xor_sync(0xffffffffu, s, off);
    if (lane == 0) g_csq[w] = s;
}

// ---------------------------------------------------------------------------
// Kernel 1: fp16 mma.sync (f16 acc) argmin search + exact fp32 recompute of
// the selected distance. BM=128, BN=128, 8 warps (4M x 2N), warp tile 32x64.
// ---------------------------------------------------------------------------
extern __shared__ char smem[];

__device__ __forceinline__ void cp_tile(uint32_t sb_dst, int t, int tid) {
    const char* src = (const char*)g_cenH + (size_t)t * BN * 512;
    #pragma unroll
    for (int s = 0; s < 16; s++) {
        int idx = tid + s * THREADS;
        int n = idx >> 5, c16 = idx & 31;
        uint32_t dst = sb_dst + n * 512 + (uint32_t)((c16 ^ (n & 7)) << 4);
        CP_ASYNC16(dst, src + n * 512 + c16 * 16);
    }
    CP_COMMIT();
}

__global__ void __launch_bounds__(THREADS, 1)
kmeans_main(const float* __restrict__ emb, const float* __restrict__ cen) {
    const uint32_t sb = smem_u32(smem);
    const int tid   = threadIdx.x;
    const int w     = tid >> 5, lane = tid & 31;
    const int tig   = lane & 3, g = lane >> 2;
    const int warpM = w >> 1, warpN = w & 1;
    const int m0    = warpM * 32;
    const uint32_t g16 = (uint32_t)g << 4;

    // kick off B tile 0 first (overlaps the A prologue)
    cp_tile(sb + SB0, 0, tid);

    // ---- A load: 2 threads per row, fp32 -> fp16, swizzled smem store ----
    {
        int row = tid >> 1, half = tid & 1;
        const float4* src = (const float4*)emb
                          + (size_t)(blockIdx.x * BM + row) * (DIM / 4) + half * 32;
        char* dstrow = smem + SAS + row * 512;
        const int key = row & 7;
        #pragma unroll
        for (int j = 0; j < 32; j++) {
            float4 v = src[j];
            int c4 = half * 32 + j;
            uint2 pk;
            pk.x = f16pair(v.x, v.y);
            pk.y = f16pair(v.z, v.w);
            *(uint2*)(dstrow + (((c4 >> 1) ^ key) << 4) + ((c4 & 1) << 3)) = pk;
        }
    }
    ((float*)(smem + SCSQ))[tid]       = g_csq[tid];
    ((float*)(smem + SCSQ))[tid + 256] = g_csq[tid + 256];

    CP_WAIT0();
    __syncthreads();

    // ---- per-thread fragment base addresses (same layout as R3) ----
    const char* aP[2][2];
    #pragma unroll
    for (int mi = 0; mi < 2; mi++)
        #pragma unroll
        for (int h = 0; h < 2; h++)
            aP[mi][h] = smem + SAS + (m0 + mi * 16 + g + 8 * h) * 512 + 4 * tig;
    uint32_t bOff[8];
    #pragma unroll
    for (int nj = 0; nj < 8; nj++)
        bOff[nj] = (uint32_t)((warpN * 64 + nj * 8 + g) * 512 + 4 * tig);

    const float* csq_s = (const float*)(smem + SCSQ);
    float rm[2][2] = {{FINF, FINF}, {FINF, FINF}};
    int   ri[2][2] = {{0, 0}, {0, 0}};

    for (int t = 0; t < NT; t++) {
        if (t + 1 < NT)
            cp_tile(sb + (((t + 1) & 1) ? SB1 : SB0), t + 1, tid);
        const char* B = smem + ((t & 1) ? SB1 : SB0);

        uint32_t c[2][8][2];
        #pragma unroll
        for (int mi = 0; mi < 2; mi++)
            #pragma unroll
            for (int nj = 0; nj < 8; nj++) { c[mi][nj][0] = 0u; c[mi][nj][1] = 0u; }

        #pragma unroll
        for (int ks = 0; ks < 16; ks++) {
            const uint32_t ka = ((uint32_t)ks << 5) ^ g16;
            const uint32_t kb = ka ^ 16u;
            uint32_t a[2][4];
            #pragma unroll
            for (int mi = 0; mi < 2; mi++) {
                a[mi][0] = *(const uint32_t*)(aP[mi][0] + ka);
                a[mi][1] = *(const uint32_t*)(aP[mi][1] + ka);
                a[mi][2] = *(const uint32_t*)(aP[mi][0] + kb);
                a[mi][3] = *(const uint32_t*)(aP[mi][1] + kb);
            }
            #pragma unroll
            for (int nj = 0; nj < 8; nj++) {
                uint32_t b0 = *(const uint32_t*)(B + bOff[nj] + ka);
                uint32_t b1 = *(const uint32_t*)(B + bOff[nj] + kb);
                mma_h(c[0][nj], a[0], b0, b1);
                mma_h(c[1][nj], a[1], b0, b1);
            }
        }

        // epilogue: cand = ||c||^2 - 2 x.c ; track (min, argmin)
        #pragma unroll
        for (int mi = 0; mi < 2; mi++)
            #pragma unroll
            for (int nj = 0; nj < 8; nj++) {
                const int col = t * BN + warpN * 64 + nj * 8 + 2 * tig;
                #pragma unroll
                for (int h = 0; h < 2; h++) {
                    __half2 hv = *(__half2*)&c[mi][nj][h];
                    float2 f = __half22float2(hv);
                    float v0 = csq_s[col]     - 2.f * f.x;
                    float v1 = csq_s[col + 1] - 2.f * f.y;
                    if (v0 < rm[mi][h]) { rm[mi][h] = v0; ri[mi][h] = col; }
                    if (v1 < rm[mi][h]) { rm[mi][h] = v1; ri[mi][h] = col + 1; }
                }
            }

        if (t + 1 < NT) { CP_WAIT0(); __syncthreads(); }
    }

    // ---- (min,idx) reduce across tig lanes, then across warpN via smem ----
    #pragma unroll
    for (int off = 1; off <= 2; off <<= 1) {
        #pragma unroll
        for (int mi = 0; mi < 2; mi++)
            #pragma unroll
            for (int h = 0; h < 2; h++) {
                float ov = __shfl_xor_sync(0xffffffffu, rm[mi][h], off);
                int   oi = __shfl_xor_sync(0xffffffffu, ri[mi][h], off);
                if (ov < rm[mi][h] || (ov == rm[mi][h] && oi < ri[mi][h])) {
                    rm[mi][h] = ov; ri[mi][h] = oi;
                }
            }
    }
    float* mv  = (float*)(smem + SMV);
    int*   mi_ = (int*)(smem + SMI);
    if (tig == 0) {
        #pragma unroll
        for (int mi = 0; mi < 2; mi++)
            #pragma unroll
            for (int h = 0; h < 2; h++) {
                int row = m0 + mi * 16 + g + 8 * h;
                mv[row * 2 + warpN]  = rm[mi][h];
                mi_[row * 2 + warpN] = ri[mi][h];
            }
    }
    __syncthreads();
    if (tid < 128) {
        float v0 = mv[2 * tid], v1 = mv[2 * tid + 1];
        int   i0 = mi_[2 * tid], i1 = mi_[2 * tid + 1];
        int best = (v1 < v0 || (v1 == v0 && i1 < i0)) ? i1 : i0;
        ((int*)(smem + SIDX))[tid] = best;
    }
    __syncthreads();

    // ---- exact fp32 recompute of the selected distance (2 threads/row) ----
    {
        const int row = tid >> 1, half = tid & 1;
        const int idx = ((const int*)(smem + SIDX))[row];
        const float4* x4 = (const float4*)emb
                         + (size_t)(blockIdx.x * BM + row) * 64 + half * 32;
        const float4* c4 = (const float4*)cen + (size_t)idx * 64 + half * 32;
        float s = 0.f;
        #pragma unroll
        for (int j = 0; j < 32; j++) {
            float4 a = x4[j], b = c4[j];
            float dx = a.x - b.x, dy = a.y - b.y;
            float dz = a.z - b.z, dw = a.w - b.w;
            s += dx * dx + dy * dy + dz * dz + dw * dw;
        }
        s += __shfl_xor_sync(0xffffffffu, s, 1);
        if (!half) ((float*)(smem + SDST))[row] = sqrtf(s);
    }
    __syncthreads();
    if (tid < 32) {
        const float* d = (const float*)(smem + SDST);
        float v = (d[tid] + d[tid + 32]) + (d[tid + 64] + d[tid + 96]);
        #pragma unroll
        for (int off = 16; off; off >>= 1)
            v += __shfl_xor_sync(0xffffffffu, v, off);
        if (tid == 0) g_partials[blockIdx.x] = v;
    }
}

// ---------------------------------------------------------------------------
// Kernel 2: deterministic tree reduce of 512 block partials -> scalar.
// ---------------------------------------------------------------------------
__global__ void finalize_kernel(float* __restrict__ out) {
    __shared__ float s[512];
    int tid = threadIdx.x;
    s[tid] = g_partials[tid];
    __syncthreads();
    #pragma unroll
    for (int off = 256; off; off >>= 1) {
        if (tid < off) s[tid] += s[tid + off];
        __syncthreads();
    }
    if (tid == 0) out[0] = s[0] * (ALPHA / (float)BATCH);
}

// ---------------------------------------------------------------------------
extern "C" void kernel_launch(void* const* d_in, const int* in_sizes, int n_in,
                              void* d_out, int out_size) {
    const float* emb;
    const float* cen;
    if (in_sizes[0] == BATCH * DIM) {
        emb = (const float*)d_in[0];
        cen = (const float*)d_in[1];
    } else {
        emb = (const float*)d_in[1];
        cen = (const float*)d_in[0];
    }
    float* out = (float*)d_out;

    cudaFuncSetAttribute(kmeans_main,
                         cudaFuncAttributeMaxDynamicSharedMemorySize, SMEM_TOTAL);

    prep_kernel<<<NUMC / 8, 256>>>(cen);
    kmeans_main<<<NBLOCKS, THREADS, SMEM_TOTAL>>>(emb, cen);
    finalize_kernel<<<1, 512>>>(out);
}

// round 7
// speedup vs baseline: 1.2335x; 1.2335x over previous
#include <cuda_runtime.h>
#include <cuda_bf16.h>
#include <cstdint>
#include <math.h>

#define BATCH   65536
#define NUMC    512
#define DIM     256
#define BM      64
#define BN      64
#define NT      (NUMC/BN)      // 8
#define THREADS 256
#define NBLOCKS (BATCH/BM)     // 1024
#define ALPHA   0.05f
#define FINF    3.402823466e38f

// smem byte offsets
#define SA      0              // A tile bf16 64x256 swizzled        (32768)
#define SB0     32768          // B buf 0 bf16 64x256                (32768)
#define SB1     65536          // B buf 1                            (32768)
#define SCSQ    98304          // 512 f                              (2048)
#define SXSQ    100352         // 64 f                               (256)
#define SMINB   100608         // 64x4 f                             (1024)
#define SDST    101632         // 64 f                               (256)
#define SMEM_TOTAL 101888

__device__ float g_csq[NUMC];
__device__ __align__(16) uint32_t g_cenB[NUMC * DIM / 2];  // bf16x2, [n][k]
__device__ float g_partials[NBLOCKS];

// ---------------- helpers ----------------
__device__ __forceinline__ uint32_t smem_u32(const void* p) {
    uint32_t a;
    asm("{ .reg .u64 t; cvta.to.shared.u64 t, %1; cvt.u32.u64 %0, t; }"
        : "=r"(a) : "l"(p));
    return a;
}
__device__ __forceinline__ uint32_t bf16pair(float lo, float hi) {
    uint32_t r;
    asm("cvt.rn.satfinite.bf16x2.f32 %0, %1, %2;" : "=r"(r) : "f"(hi), "f"(lo));
    return r;
}
__device__ __forceinline__ void mma16816(float c[4], const uint32_t a[4],
                                         uint32_t b0, uint32_t b1) {
    asm volatile(
        "mma.sync.aligned.m16n8k16.row.col.f32.bf16.bf16.f32 "
        "{%0,%1,%2,%3}, {%4,%5,%6,%7}, {%8,%9}, {%0,%1,%2,%3};"
        : "+f"(c[0]), "+f"(c[1]), "+f"(c[2]), "+f"(c[3])
        : "r"(a[0]), "r"(a[1]), "r"(a[2]), "r"(a[3]), "r"(b0), "r"(b1));
}
#define CP_ASYNC16(dst, src) \
    asm volatile("cp.async.cg.shared.global [%0], [%1], 16;" :: "r"(dst), "l"(src))
#define CP_COMMIT()  asm volatile("cp.async.commit_group;" ::: "memory")
#define CP_WAIT0()   asm volatile("cp.async.wait_group 0;" ::: "memory")

// ---------------------------------------------------------------------------
// Kernel 0: center norms (exact fp32) + bf16 copy of centers, [n][k] layout.
// ---------------------------------------------------------------------------
__global__ void prep_kernel(const float* __restrict__ cen) {
    int w    = blockIdx.x * 8 + (threadIdx.x >> 5);
    int lane = threadIdx.x & 31;
    const float2* row = (const float2*)(cen + (size_t)w * DIM);
    float s = 0.f;
    #pragma unroll
    for (int i = 0; i < 4; i++) {
        float2 v = row[lane + 32 * i];
        s += v.x * v.x + v.y * v.y;
        g_cenB[w * (DIM / 2) + lane + 32 * i] = bf16pair(v.x, v.y);
    }
    #pragma unroll
    for (int off = 16; off; off >>= 1)
        s += __shfl_xor_sync(0xffffffffu, s, off);
    if (lane == 0) g_csq[w] = s;
}

// ---------------------------------------------------------------------------
// Kernel 1: bf16 mma.sync GEMM fused with row-min + sqrt + block reduction.
// BM=64 (1024 CTAs, near-perfect wave balance), occupancy 2.
// 8 warps as 2M x 4N; warp tile 32x16.
// ---------------------------------------------------------------------------
extern __shared__ char smem[];

__device__ __forceinline__ void cp_tile(uint32_t sb_dst, int t, int tid) {
    const char* src = (const char*)g_cenB + (size_t)t * BN * 512;
    #pragma unroll
    for (int s = 0; s < 8; s++) {
        int idx = tid + s * THREADS;
        int n = idx >> 5, c16 = idx & 31;
        uint32_t dst = sb_dst + n * 512 + (uint32_t)((c16 ^ (n & 7)) << 4);
        CP_ASYNC16(dst, src + n * 512 + c16 * 16);
    }
    CP_COMMIT();
}

__global__ void __launch_bounds__(THREADS, 2)
kmeans_main(const float* __restrict__ emb) {
    const uint32_t sb = smem_u32(smem);
    const int tid   = threadIdx.x;
    const int w     = tid >> 5, lane = tid & 31;
    const int tig   = lane & 3, g = lane >> 2;
    const int warpM = w >> 2, warpN = w & 3;
    const int m0    = warpM * 32;
    const uint32_t g16 = (uint32_t)g << 4;

    // kick off B tile 0 first (overlaps the A prologue)
    cp_tile(sb + SB0, 0, tid);

    // ---- A load: 4 threads/row, fp32 -> bf16, swizzled store, exact xsq ----
    {
        const int row = tid >> 2, part = tid & 3;
        const float4* src = (const float4*)emb
                          + (size_t)(blockIdx.x * BM + row) * (DIM / 4) + part * 16;
        char* dstrow = smem + SA + row * 512;
        const int key = row & 7;
        float xs = 0.f;
        #pragma unroll
        for (int j = 0; j < 16; j++) {
            float4 v = src[j];
            xs += v.x * v.x + v.y * v.y + v.z * v.z + v.w * v.w;
            int c4 = part * 16 + j;
            uint2 pk;
            pk.x = bf16pair(v.x, v.y);
            pk.y = bf16pair(v.z, v.w);
            *(uint2*)(dstrow + (((c4 >> 1) ^ key) << 4) + ((c4 & 1) << 3)) = pk;
        }
        xs += __shfl_xor_sync(0xffffffffu, xs, 1);
        xs += __shfl_xor_sync(0xffffffffu, xs, 2);
        if (part == 0) ((float*)(smem + SXSQ))[row] = xs;
    }
    ((float*)(smem + SCSQ))[tid]       = g_csq[tid];
    ((float*)(smem + SCSQ))[tid + 256] = g_csq[tid + 256];

    CP_WAIT0();
    __syncthreads();

    // ---- per-thread fragment base addresses (R3-proven layout) ----
    const char* aP[2][2];
    #pragma unroll
    for (int mi = 0; mi < 2; mi++)
        #pragma unroll
        for (int h = 0; h < 2; h++)
            aP[mi][h] = smem + SA + (m0 + mi * 16 + g + 8 * h) * 512 + 4 * tig;
    uint32_t bOff[2];
    #pragma unroll
    for (int nj = 0; nj < 2; nj++)
        bOff[nj] = (uint32_t)((warpN * 16 + nj * 8 + g) * 512 + 4 * tig);

    const float* csq_s = (const float*)(smem + SCSQ);
    float rm[2][2] = {{FINF, FINF}, {FINF, FINF}};

    for (int t = 0; t < NT; t++) {
        if (t + 1 < NT)
            cp_tile(sb + (((t + 1) & 1) ? SB1 : SB0), t + 1, tid);
        const char* B = smem + ((t & 1) ? SB1 : SB0);

        float c[2][2][4];
        #pragma unroll
        for (int mi = 0; mi < 2; mi++)
            #pragma unroll
            for (int nj = 0; nj < 2; nj++)
                #pragma unroll
                for (int q = 0; q < 4; q++) c[mi][nj][q] = 0.f;

        #pragma unroll
        for (int ks = 0; ks < 16; ks++) {
            const uint32_t ka = ((uint32_t)ks << 5) ^ g16;
            const uint32_t kb = ka ^ 16u;
            uint32_t a[2][4];
            #pragma unroll
            for (int mi = 0; mi < 2; mi++) {
                a[mi][0] = *(const uint32_t*)(aP[mi][0] + ka);
                a[mi][1] = *(const uint32_t*)(aP[mi][1] + ka);
                a[mi][2] = *(const uint32_t*)(aP[mi][0] + kb);
                a[mi][3] = *(const uint32_t*)(aP[mi][1] + kb);
            }
            #pragma unroll
            for (int nj = 0; nj < 2; nj++) {
                uint32_t b0 = *(const uint32_t*)(B + bOff[nj] + ka);
                uint32_t b1 = *(const uint32_t*)(B + bOff[nj] + kb);
                mma16816(c[0][nj], a[0], b0, b1);
                mma16816(c[1][nj], a[1], b0, b1);
            }
        }

        // epilogue: cand = ||c||^2 - 2 x.c ; running min
        #pragma unroll
        for (int mi = 0; mi < 2; mi++)
            #pragma unroll
            for (int nj = 0; nj < 2; nj++) {
                int col = t * BN + warpN * 16 + nj * 8 + 2 * tig;
                float q0 = csq_s[col]     - 2.f * c[mi][nj][0];
                float q1 = csq_s[col + 1] - 2.f * c[mi][nj][1];
                float q2 = csq_s[col]     - 2.f * c[mi][nj][2];
                float q3 = csq_s[col + 1] - 2.f * c[mi][nj][3];
                rm[mi][0] = fminf(rm[mi][0], fminf(q0, q1));
                rm[mi][1] = fminf(rm[mi][1], fminf(q2, q3));
            }

        if (t + 1 < NT) { CP_WAIT0(); __syncthreads(); }
    }

    // ---- reduction: min across tig lanes, across 4 warpN warps, sqrt, sum --
    float* minb = (float*)(smem + SMINB);
    #pragma unroll
    for (int mi = 0; mi < 2; mi++)
        #pragma unroll
        for (int h = 0; h < 2; h++) {
            float v = rm[mi][h];
            v = fminf(v, __shfl_xor_sync(0xffffffffu, v, 1));
            v = fminf(v, __shfl_xor_sync(0xffffffffu, v, 2));
            if (tig == 0)
                minb[(m0 + mi * 16 + g + 8 * h) * 4 + warpN] = v;
        }
    __syncthreads();
    if (tid < 64) {
        float m = fminf(fminf(minb[4 * tid], minb[4 * tid + 1]),
                        fminf(minb[4 * tid + 2], minb[4 * tid + 3]));
        float xs = ((float*)(smem + SXSQ))[tid];
        ((float*)(smem + SDST))[tid] = sqrtf(fmaxf(xs + m, 0.f));
    }
    __syncthreads();
    if (tid < 32) {
        const float* d = (const float*)(smem + SDST);
        float v = d[tid] + d[tid + 32];
        #pragma unroll
        for (int off = 16; off; off >>= 1)
            v += __shfl_xor_sync(0xffffffffu, v, off);
        if (tid == 0) g_partials[blockIdx.x] = v;
    }
}

// ---------------------------------------------------------------------------
// Kernel 2: deterministic tree reduce of 1024 block partials -> scalar.
// ---------------------------------------------------------------------------
__global__ void finalize_kernel(float* __restrict__ out) {
    __shared__ float s[512];
    int tid = threadIdx.x;
    s[tid] = g_partials[tid] + g_partials[tid + 512];
    __syncthreads();
    #pragma unroll
    for (int off = 256; off; off >>= 1) {
        if (tid < off) s[tid] += s[tid + off];
        __syncthreads();
    }
    if (tid == 0) out[0] = s[0] * (ALPHA / (float)BATCH);
}

// ---------------------------------------------------------------------------
extern "C" void kernel_launch(void* const* d_in, const int* in_sizes, int n_in,
                              void* d_out, int out_size) {
    const float* emb;
    const float* cen;
    if (in_sizes[0] == BATCH * DIM) {
        emb = (const float*)d_in[0];
        cen = (const float*)d_in[1];
    } else {
        emb = (const float*)d_in[1];
        cen = (const float*)d_in[0];
    }
    float* out = (float*)d_out;

    cudaFuncSetAttribute(kmeans_main,
                         cudaFuncAttributeMaxDynamicSharedMemorySize, SMEM_TOTAL);

    prep_kernel<<<NUMC / 8, 256>>>(cen);
    kmeans_main<<<NBLOCKS, THREADS, SMEM_TOTAL>>>(emb);
    finalize_kernel<<<1, 512>>>(out);
}